// round 17
// baseline (speedup 1.0000x reference)
#include <cuda_runtime.h>
#include <cuda_fp16.h>
#include <math.h>

#define NCTA 128
#define NTH  512
#define Bsz  256
#define Tlen 1024
#define Hdim 256

#define ROWB 528                        // 264 halfs per smem row
#define OFF_S0 0                        // h0 slab: 32 rows
#define OFF_S1 16896                    // h1 slab: 32 rows
#define OFF_W1 33792                    // Whh1 fp16 [n=64][k=256] rows 264
#define DYN_SMEM (33792 + 64 * ROWB)    // 67584 B

// Persistent h state, fp16, layout [b][k], double-buffered by parity.
// Parity p holds (h0(t), h1(t-1)) for t with t&1 == p.
__device__ __half g_h0[2][Bsz * Hdim];
__device__ __half g_h1[2][Bsz * Hdim];
__device__ float g_xT[Tlen * Bsz];
__device__ unsigned g_cnt = 0, g_done = 0;
// per-batch-group barrier counters, 128 B apart (independent lines)
__device__ unsigned g_gcnt[8 * 32];

__device__ __forceinline__ float sigf(float x) {
    return __fdividef(1.0f, 1.0f + __expf(-x));
}
__device__ __forceinline__ float tanhf_(float x) {
    return fmaf(2.0f, sigf(2.0f * x), -1.0f);
}
__device__ __forceinline__ unsigned smem_u32(const void* p) {
    unsigned a;
    asm("{ .reg .u64 t; cvta.to.shared.u64 t, %1; cvt.u32.u64 %0, t; }"
        : "=r"(a) : "l"(p));
    return a;
}
__device__ __forceinline__ unsigned packh2(float a, float b) {
    __half2 h = __floats2half2_rn(a, b);
    return *reinterpret_cast<unsigned*>(&h);
}
__device__ __forceinline__ void ldm_x4(unsigned addr, unsigned& r0, unsigned& r1,
                                       unsigned& r2, unsigned& r3) {
    asm volatile("ldmatrix.sync.aligned.m8n8.x4.shared.b16 {%0,%1,%2,%3}, [%4];"
                 : "=r"(r0), "=r"(r1), "=r"(r2), "=r"(r3) : "r"(addr) : "memory");
}
__device__ __forceinline__ void mma16816(float* d, unsigned a0, unsigned a1,
                                         unsigned a2, unsigned a3,
                                         unsigned b0, unsigned b1) {
    asm volatile("mma.sync.aligned.m16n8k16.row.col.f32.f16.f16.f32 "
                 "{%0,%1,%2,%3}, {%4,%5,%6,%7}, {%8,%9}, {%0,%1,%2,%3};"
                 : "+f"(d[0]), "+f"(d[1]), "+f"(d[2]), "+f"(d[3])
                 : "r"(a0), "r"(a1), "r"(a2), "r"(a3), "r"(b0), "r"(b1));
}

// Split-phase barrier (works for global line or per-group line).
__device__ __forceinline__ void bar_arrive(unsigned* c) {
    __syncthreads();
    if (threadIdx.x == 0) {
        asm volatile("red.release.gpu.global.add.u32 [%0], %1;"
                     :: "l"(c), "r"(1u) : "memory");
    }
}
__device__ __forceinline__ void bar_wait(unsigned* c, unsigned target) {
    if (threadIdx.x == 0) {
        unsigned v;
        do {
            asm volatile("ld.acquire.gpu.u32 %0, [%1];" : "=r"(v) : "l"(c));
        } while (v < target);
    }
    __syncthreads();
}

__global__ void __launch_bounds__(NTH, 1)
lstm_mma3(const float* __restrict__ x,
          const float* __restrict__ Wih0, const float* __restrict__ Whh0,
          const float* __restrict__ bih0, const float* __restrict__ bhh0,
          const float* __restrict__ Wih1, const float* __restrict__ Whh1,
          const float* __restrict__ bih1, const float* __restrict__ bhh1,
          const float* __restrict__ Wlin, const float* __restrict__ blin,
          float* __restrict__ out)
{
    extern __shared__ char dsm[];
    __shared__ float  sG[32 * 136];      // gates [batch][col]; cols 0-63 L0, 64-127 L1
    __shared__ float4 sW4[64];           // Wlin quads
    __shared__ float  sWx[64], sB0[64], sB1[64];   // per gate col = q*16+uloc
    __shared__ float  sOut[4];

    const int tid = threadIdx.x, lane = tid & 31, warp = tid >> 5;
    const int cta = blockIdx.x;
    const int ug = cta >> 3, bg = cta & 7;   // 16 unit-groups x 8 batch-groups
    const int ub = 16 * ug, bb = 32 * bg;
    const int mt = warp >> 3;                // batch-row tile 0/1
    const int n0 = (warp & 7) * 8;           // gate-col tile base

    unsigned* gbar = &g_gcnt[bg * 32];       // this group's barrier line

    // activation role: 32 batches x 16 units
    const int bloc = tid >> 4, ul = tid & 15;
    const int gb = bb + bloc, gu = ub + ul;

    // fragment lane mapping (m16n8k16)
    const int fr = lane >> 2;                // 0..7
    const int fc = (lane & 3) * 2;           // k offset within tile
    const int nmy = n0 + fr;                 // my gate col 0..63
    const int grow = (nmy >> 4) * 256 + ub + (nmy & 15);  // global gate row

    // output-gather role (tid < 128): batches WITHIN this batch-group
    const int ob = bb + 2 * ug + (tid >> 6);
    const int okq = tid & 63;

    // ---- one-time staging ----
    for (int i = cta * NTH + tid; i < Bsz * Tlen; i += NCTA * NTH) {
        int b = i >> 10, t = i & (Tlen - 1);
        g_xT[t * Bsz + b] = x[i];
    }
    for (int e = tid; e < 64 * 256; e += NTH) {      // Whh1 fp16 [n][k]
        int n = e >> 8, k = e & 255;
        int gr = (n >> 4) * 256 + ub + (n & 15);
        ((__half*)(dsm + OFF_W1))[n * 264 + k] = __float2half(Whh1[gr * 256 + k]);
    }
    if (tid < 64) {
        int gr = (tid >> 4) * 256 + ub + (tid & 15);
        sWx[tid] = Wih0[gr];
        sB0[tid] = bih0[gr] + bhh0[gr];
        sB1[tid] = bih1[gr] + bhh1[gr];
        sW4[tid] = ((const float4*)Wlin)[tid];
    }
    const float bl = __ldg(blin);

    // weight B-fragments in registers (loaded once, fp32->fp16)
    unsigned w0f[16][2], wif[16][2];
    {
        const float* r0 = Whh0 + grow * 256;
        const float* r1 = Wih1 + grow * 256;
        #pragma unroll
        for (int kt = 0; kt < 16; ++kt) {
            int k = kt * 16 + fc;
            w0f[kt][0] = packh2(r0[k],     r0[k + 1]);
            w0f[kt][1] = packh2(r0[k + 8], r0[k + 9]);
            wif[kt][0] = packh2(r1[k],     r1[k + 1]);
            wif[kt][1] = packh2(r1[k + 8], r1[k + 9]);
        }
    }

    g_h1[0][gb * Hdim + gu] = __float2half(0.0f);    // h1(-1) = 0
    float c0 = 0.f, c1 = 0.f;

    bar_arrive(&g_cnt); bar_wait(&g_cnt, 1u * NCTA);   // global: staging visible

    // ---- prologue: h0(0) from zero state ----
    {
        float xv = g_xT[gb];
        float gi = fmaf(sWx[0*16 + ul], xv, sB0[0*16 + ul]);
        float gg = fmaf(sWx[2*16 + ul], xv, sB0[2*16 + ul]);
        float go = fmaf(sWx[3*16 + ul], xv, sB0[3*16 + ul]);
        float cn = sigf(gi) * tanhf_(gg);
        c0 = cn;
        g_h0[0][gb * Hdim + gu] = __float2half(sigf(go) * tanhf_(cn));
    }
    bar_arrive(&g_cnt); bar_wait(&g_cnt, 2u * NCTA);   // global: h0(0) visible

    const unsigned sb = smem_u32(dsm);
    // ldmatrix A base: lanes 0-15 -> rows, lanes 16-31 -> rows at k+8
    const unsigned aL = sb + (mt * 16 + (lane & 15)) * ROWB + ((lane >> 4) & 1) * 16;
    const char* w1p = dsm + OFF_W1 + nmy * ROWB + fc * 2;

    for (int t = 0; t < Tlen; ++t) {
        const int p = t & 1, nx = p ^ 1;
        const __half* h0p = g_h0[p];
        const __half* h1p = g_h1[p];

        // output operand prefetch: h1(t-1) at parity p (own batch-group)
        unsigned long long hpref = 0ull;
        if (tid < 128)
            hpref = *(const unsigned long long*)(h1p + ob * Hdim + 4 * okq);

        // ---- stage h slabs (32 batches x 256 k, both layers) ----
        for (int idx = tid; idx < 2048; idx += NTH) {
            int sl = idx >> 10, rr = (idx >> 5) & 31, c16 = idx & 31;
            const __half* src = (sl ? h1p : h0p) + (bb + rr) * Hdim + c16 * 8;
            uint4 v = __ldcg((const uint4*)src);
            *(uint4*)(dsm + (sl ? OFF_S1 : OFF_S0) + rr * ROWB + c16 * 16) = v;
        }
        __syncthreads();

        // ---- MMA: d0 = L0 gates (Whh0@h0), d1 = L1 gates (Wih1@h0 + Whh1@h1) ----
        float d0[4] = {0.f, 0.f, 0.f, 0.f};
        float d1[4] = {0.f, 0.f, 0.f, 0.f};
        #pragma unroll
        for (int kt = 0; kt < 16; ++kt) {
            unsigned A0, A1, A2, A3;
            ldm_x4(aL + OFF_S0 + kt * 32, A0, A1, A2, A3);
            mma16816(d0, A0, A1, A2, A3, w0f[kt][0], w0f[kt][1]);
            mma16816(d1, A0, A1, A2, A3, wif[kt][0], wif[kt][1]);
        }
        #pragma unroll
        for (int kt = 0; kt < 16; ++kt) {
            unsigned A0, A1, A2, A3;
            ldm_x4(aL + OFF_S1 + kt * 32, A0, A1, A2, A3);
            unsigned b0 = *(const unsigned*)(w1p + kt * 32);
            unsigned b1 = *(const unsigned*)(w1p + kt * 32 + 16);
            mma16816(d1, A0, A1, A2, A3, b0, b1);
        }

        // ---- scatter gates to sG[batch][col] ----
        {
            int r = mt * 16 + fr, c = n0 + fc;
            *(float2*)&sG[r * 136 + c]            = make_float2(d0[0], d0[1]);
            *(float2*)&sG[(r + 8) * 136 + c]      = make_float2(d0[2], d0[3]);
            *(float2*)&sG[r * 136 + 64 + c]       = make_float2(d1[0], d1[1]);
            *(float2*)&sG[(r + 8) * 136 + 64 + c] = make_float2(d1[2], d1[3]);
        }
        __syncthreads();

        // ---- activations (fp32 cell state, fp16 h publish) ----
        {   // layer 1: h1(t)
            float gi = sG[bloc * 136 + 64 + 0*16 + ul] + sB1[0*16 + ul];
            float gf = sG[bloc * 136 + 64 + 1*16 + ul] + sB1[1*16 + ul];
            float gg = sG[bloc * 136 + 64 + 2*16 + ul] + sB1[2*16 + ul];
            float go = sG[bloc * 136 + 64 + 3*16 + ul] + sB1[3*16 + ul];
            float cn = sigf(gf) * c1 + sigf(gi) * tanhf_(gg);
            c1 = cn;
            g_h1[nx][gb * Hdim + gu] = __float2half(sigf(go) * tanhf_(cn));
        }
        if (t < Tlen - 1) {  // layer 0: h0(t+1)
            float xv = g_xT[(t + 1) * Bsz + gb];
            float gi = sG[bloc * 136 + 0*16 + ul] + fmaf(sWx[0*16 + ul], xv, sB0[0*16 + ul]);
            float gf = sG[bloc * 136 + 1*16 + ul] + fmaf(sWx[1*16 + ul], xv, sB0[1*16 + ul]);
            float gg = sG[bloc * 136 + 2*16 + ul] + fmaf(sWx[2*16 + ul], xv, sB0[2*16 + ul]);
            float go = sG[bloc * 136 + 3*16 + ul] + fmaf(sWx[3*16 + ul], xv, sB0[3*16 + ul]);
            float cn = sigf(gf) * c0 + sigf(gi) * tanhf_(gg);
            c0 = cn;
            g_h0[nx][gb * Hdim + gu] = __float2half(sigf(go) * tanhf_(cn));
        }

        bar_arrive(gbar);                    // GROUP barrier (16 CTAs)

        if (t >= 1) {                        // output in the wait shadow
            if (tid < 128) {
                unsigned lo_u = (unsigned)hpref, hi_u = (unsigned)(hpref >> 32);
                float2 lo = __half22float2(*(__half2*)&lo_u);
                float2 hi = __half22float2(*(__half2*)&hi_u);
                float4 wl = sW4[okq];
                float part = lo.x * wl.x + lo.y * wl.y + hi.x * wl.z + hi.y * wl.w;
                #pragma unroll
                for (int off = 16; off > 0; off >>= 1)
                    part += __shfl_down_sync(0xffffffffu, part, off);
                if ((tid & 31) == 0) sOut[tid >> 5] = part;
            }
            __syncthreads();
            if (tid == 0) {
                out[(ob - (tid >> 6)) * Tlen + (t - 1)]     = sOut[0] + sOut[1] + bl;
                out[(ob - (tid >> 6) + 1) * Tlen + (t - 1)] = sOut[2] + sOut[3] + bl;
            }
        }

        bar_wait(gbar, (unsigned)(t + 1) * 16u);
    }

    // ---- final output(1023): h1(1023) at parity 0 ----
    {
        if (tid < 128) {
            unsigned long long hv =
                *(const unsigned long long*)(g_h1[0] + ob * Hdim + 4 * okq);
            unsigned lo_u = (unsigned)hv, hi_u = (unsigned)(hv >> 32);
            float2 lo = __half22float2(*(__half2*)&lo_u);
            float2 hi = __half22float2(*(__half2*)&hi_u);
            float4 wl = sW4[okq];
            float part = lo.x * wl.x + lo.y * wl.y + hi.x * wl.z + hi.y * wl.w;
            #pragma unroll
            for (int off = 16; off > 0; off >>= 1)
                part += __shfl_down_sync(0xffffffffu, part, off);
            if ((tid & 31) == 0) sOut[tid >> 5] = part;
        }
        __syncthreads();
        if (tid == 0) {
            out[(bb + 2 * ug + 0) * Tlen + (Tlen - 1)] = sOut[0] + sOut[1] + bl;
            out[(bb + 2 * ug + 1) * Tlen + (Tlen - 1)] = sOut[2] + sOut[3] + bl;
        }
    }

    // reset counters for next launch
    __syncthreads();
    if (tid == 0) {
        __threadfence();
        unsigned old = atomicAdd(&g_done, 1u);
        if (old == NCTA - 1) {
            atomicExch(&g_cnt, 0u);
            for (int g = 0; g < 8; ++g) atomicExch(&g_gcnt[g * 32], 0u);
            atomicExch(&g_done, 0u);
        }
    }
}

extern "C" void kernel_launch(void* const* d_in, const int* in_sizes, int n_in,
                              void* d_out, int out_size) {
    (void)in_sizes; (void)n_in; (void)out_size;
    cudaFuncSetAttribute(lstm_mma3, cudaFuncAttributeMaxDynamicSharedMemorySize,
                         DYN_SMEM);
    lstm_mma3<<<NCTA, NTH, DYN_SMEM>>>(
        (const float*)d_in[0],
        (const float*)d_in[1], (const float*)d_in[2],
        (const float*)d_in[3], (const float*)d_in[4],
        (const float*)d_in[5], (const float*)d_in[6],
        (const float*)d_in[7], (const float*)d_in[8],
        (const float*)d_in[9], (const float*)d_in[10],
        (float*)d_out);
}